// round 1
// baseline (speedup 1.0000x reference)
#include <cuda_runtime.h>
#include <math.h>

// Problem constants
#define CB 2
#define CS 2048
#define CD 1024
#define CH 16
#define CDK 64
#define CM (CB*CS)   // 4096 rows

// Scratch (device globals: allocation-free rule)
__device__ float g_q[CB*CS*CD];
__device__ float g_k[CB*CS*CD];
__device__ float g_v[CB*CS*CD];
__device__ float g_a[CB*CS*CD];

// ---------------------------------------------------------------------------
// SGEMM: C[M,N] = A[M,K] * B[N,K]^T   (both operands K-major, row-major)
// 128x128 block tile, BK=16, 256 threads, 8x8 per-thread register tile.
// M,N,K all multiples of tile dims for this problem -> no bounds checks.
// ---------------------------------------------------------------------------
#define BM 128
#define BN 128
#define BKK 16

__global__ void __launch_bounds__(256) sgemm_nt(const float* __restrict__ A,
                                                const float* __restrict__ B,
                                                float* __restrict__ C,
                                                int M, int N, int K)
{
    __shared__ float As[BKK][BM + 4];
    __shared__ float Bs[BKK][BN + 4];

    const int tid = threadIdx.x;
    const int tx = tid & 15;     // 0..15 -> col group
    const int ty = tid >> 4;     // 0..15 -> row group
    const int row0 = blockIdx.y * BM;
    const int col0 = blockIdx.x * BN;

    const int lr = tid >> 2;          // 0..63 loader row
    const int lc = (tid & 3) << 2;    // 0,4,8,12 loader col (float4)

    float acc[8][8];
    #pragma unroll
    for (int i = 0; i < 8; i++)
        #pragma unroll
        for (int j = 0; j < 8; j++) acc[i][j] = 0.f;

    for (int k0 = 0; k0 < K; k0 += BKK) {
        #pragma unroll
        for (int hh = 0; hh < 2; hh++) {
            const int r = lr + hh * 64;
            float4 va = *(const float4*)&A[(size_t)(row0 + r) * K + k0 + lc];
            As[lc + 0][r] = va.x; As[lc + 1][r] = va.y;
            As[lc + 2][r] = va.z; As[lc + 3][r] = va.w;
            float4 vb = *(const float4*)&B[(size_t)(col0 + r) * K + k0 + lc];
            Bs[lc + 0][r] = vb.x; Bs[lc + 1][r] = vb.y;
            Bs[lc + 2][r] = vb.z; Bs[lc + 3][r] = vb.w;
        }
        __syncthreads();

        #pragma unroll
        for (int kk = 0; kk < BKK; kk++) {
            const float4* ar = (const float4*)&As[kk][0];
            const float4* br = (const float4*)&Bs[kk][0];
            float4 a0 = ar[ty * 2], a1 = ar[ty * 2 + 1];
            float4 b0 = br[tx * 2], b1 = br[tx * 2 + 1];
            float a[8] = {a0.x, a0.y, a0.z, a0.w, a1.x, a1.y, a1.z, a1.w};
            float b[8] = {b0.x, b0.y, b0.z, b0.w, b1.x, b1.y, b1.z, b1.w};
            #pragma unroll
            for (int i = 0; i < 8; i++)
                #pragma unroll
                for (int j = 0; j < 8; j++)
                    acc[i][j] = fmaf(a[i], b[j], acc[i][j]);
        }
        __syncthreads();
    }

    #pragma unroll
    for (int i = 0; i < 8; i++) {
        float4 o0 = make_float4(acc[i][0], acc[i][1], acc[i][2], acc[i][3]);
        float4 o1 = make_float4(acc[i][4], acc[i][5], acc[i][6], acc[i][7]);
        float* cp = &C[(size_t)(row0 + ty * 8 + i) * N + col0 + tx * 8];
        *(float4*)(cp + 0) = o0;
        *(float4*)(cp + 4) = o1;
    }
}

// ---------------------------------------------------------------------------
// Causal flash attention. Layout: q/k/v/o are [B,S,D] with head h occupying
// columns [h*64, h*64+64). Grid: (S/128, B*H). 128 threads, one query each.
// 32-key K/V tiles in smem, online softmax, DK=64 fp32 accumulator in regs.
// ---------------------------------------------------------------------------
__global__ void __launch_bounds__(128) attn_kernel(const float* __restrict__ qg,
                                                   const float* __restrict__ kg,
                                                   const float* __restrict__ vg,
                                                   float* __restrict__ og)
{
    const int bh = blockIdx.y;
    const int b  = bh >> 4;
    const int h  = bh & 15;
    const int q0 = blockIdx.x * 128;
    const int t  = threadIdx.x;
    const int qi = q0 + t;

    __shared__ float4 Ks[32][16];
    __shared__ float4 Vs[32][16];

    float4 qr[16];
    const float4* qp = (const float4*)(qg + ((size_t)(b * CS + qi)) * CD + h * CDK);
    #pragma unroll
    for (int i = 0; i < 16; i++) qr[i] = qp[i];

    float4 acc[16];
    #pragma unroll
    for (int i = 0; i < 16; i++) acc[i] = make_float4(0.f, 0.f, 0.f, 0.f);
    float m = -1e30f, l = 0.f;

    const int lr = t >> 2;   // 0..31 loader row
    const int lc = t & 3;    // quarter of a 64-float row
    const int ntiles = q0 / 32 + 4;   // covers keys 0 .. q0+127

    for (int kt = 0; kt < ntiles; kt++) {
        const int k0 = kt * 32;
        const float4* kp = (const float4*)(kg + ((size_t)(b * CS + k0 + lr)) * CD + h * CDK);
        const float4* vp = (const float4*)(vg + ((size_t)(b * CS + k0 + lr)) * CD + h * CDK);
        #pragma unroll
        for (int j = 0; j < 4; j++) {
            Ks[lr][lc * 4 + j] = kp[lc * 4 + j];
            Vs[lr][lc * 4 + j] = vp[lc * 4 + j];
        }
        __syncthreads();

        float sc[32];
        #pragma unroll
        for (int j = 0; j < 32; j++) {
            float sx = 0.f, sy = 0.f, sz = 0.f, sw = 0.f;
            #pragma unroll
            for (int d = 0; d < 16; d++) {
                float4 kk = Ks[j][d];
                sx = fmaf(qr[d].x, kk.x, sx);
                sy = fmaf(qr[d].y, kk.y, sy);
                sz = fmaf(qr[d].z, kk.z, sz);
                sw = fmaf(qr[d].w, kk.w, sw);
            }
            float s = ((sx + sy) + (sz + sw)) * 0.125f;  // 1/sqrt(64)
            sc[j] = (k0 + j > qi) ? -1e30f : s;
        }

        float mt = m;
        #pragma unroll
        for (int j = 0; j < 32; j++) mt = fmaxf(mt, sc[j]);
        float corr = __expf(m - mt);
        l *= corr;
        #pragma unroll
        for (int i = 0; i < 16; i++) {
            acc[i].x *= corr; acc[i].y *= corr;
            acc[i].z *= corr; acc[i].w *= corr;
        }
        #pragma unroll
        for (int j = 0; j < 32; j++) {
            float p = __expf(sc[j] - mt);
            l += p;
            #pragma unroll
            for (int d = 0; d < 16; d++) {
                float4 vv = Vs[j][d];
                acc[d].x = fmaf(p, vv.x, acc[d].x);
                acc[d].y = fmaf(p, vv.y, acc[d].y);
                acc[d].z = fmaf(p, vv.z, acc[d].z);
                acc[d].w = fmaf(p, vv.w, acc[d].w);
            }
        }
        m = mt;
        __syncthreads();
    }

    const float inv = 1.0f / l;
    float4* op = (float4*)(og + ((size_t)(b * CS + qi)) * CD + h * CDK);
    #pragma unroll
    for (int i = 0; i < 16; i++)
        op[i] = make_float4(acc[i].x * inv, acc[i].y * inv, acc[i].z * inv, acc[i].w * inv);
}

// ---------------------------------------------------------------------------
// Launch. Input order (metadata): Q, K, V, mask(ignored, causal is known),
// w_q, w_k, w_v, w_o. Output: [B,S,D] float32.
// ---------------------------------------------------------------------------
extern "C" void kernel_launch(void* const* d_in, const int* in_sizes, int n_in,
                              void* d_out, int out_size)
{
    const float* Q  = (const float*)d_in[0];
    const float* K  = (const float*)d_in[1];
    const float* V  = (const float*)d_in[2];
    const float* wq = (const float*)d_in[4];
    const float* wk = (const float*)d_in[5];
    const float* wv = (const float*)d_in[6];
    const float* wo = (const float*)d_in[7];
    float* out = (float*)d_out;

    float *qb, *kb, *vb, *ab;
    cudaGetSymbolAddress((void**)&qb, g_q);
    cudaGetSymbolAddress((void**)&kb, g_k);
    cudaGetSymbolAddress((void**)&vb, g_v);
    cudaGetSymbolAddress((void**)&ab, g_a);

    dim3 gg(CD / BN, CM / BM);   // (8, 32)
    sgemm_nt<<<gg, 256>>>(Q, wq, qb, CM, CD, CD);
    sgemm_nt<<<gg, 256>>>(K, wk, kb, CM, CD, CD);
    sgemm_nt<<<gg, 256>>>(V, wv, vb, CM, CD, CD);

    attn_kernel<<<dim3(CS / 128, CB * CH), 128>>>(qb, kb, vb, ab);

    sgemm_nt<<<gg, 256>>>(ab, wo, out, CM, CD, CD);
}

// round 3
// speedup vs baseline: 1.3778x; 1.3778x over previous
#include <cuda_runtime.h>
#include <cstdint>
#include <math.h>

// Problem constants
#define CB 2
#define CS 2048
#define CD 1024
#define CH 16
#define CDK 64
#define CM (CB*CS)   // 4096 rows

// Scratch (device globals: allocation-free rule)
__device__ float g_q[CB*CS*CD];
__device__ float g_k[CB*CS*CD];
__device__ float g_v[CB*CS*CD];
__device__ float g_a[CB*CS*CD];

// ---------------------------------------------------------------------------
// Helpers
// ---------------------------------------------------------------------------
__device__ __forceinline__ uint32_t smem_u32(const void* p) {
    uint32_t a;
    asm("{ .reg .u64 t; cvta.to.shared.u64 t, %1; cvt.u32.u64 %0, t; }" : "=r"(a) : "l"(p));
    return a;
}
__device__ __forceinline__ void cp_async16(uint32_t dst, const void* src) {
    asm volatile("cp.async.cg.shared.global [%0], [%1], 16;" :: "r"(dst), "l"(src) : "memory");
}
#define CP_COMMIT() asm volatile("cp.async.commit_group;" ::: "memory")
#define CP_WAIT(n)  asm volatile("cp.async.wait_group %0;" :: "n"(n) : "memory")

__device__ __forceinline__ uint32_t f2tf32(float x) {
    uint32_t o;
    asm("cvt.rna.tf32.f32 %0, %1;" : "=r"(o) : "f"(x));
    return o;
}
__device__ __forceinline__ void mma_tf32(float c[4], const uint32_t a[4], const uint32_t b[2]) {
    asm volatile("mma.sync.aligned.m16n8k8.row.col.f32.tf32.tf32.f32 "
                 "{%0,%1,%2,%3}, {%4,%5,%6,%7}, {%8,%9}, {%0,%1,%2,%3};"
                 : "+f"(c[0]), "+f"(c[1]), "+f"(c[2]), "+f"(c[3])
                 : "r"(a[0]), "r"(a[1]), "r"(a[2]), "r"(a[3]), "r"(b[0]), "r"(b[1]));
}

// ---------------------------------------------------------------------------
// TF32 tensor-core GEMM: C[M,N] = A[M,K] * B[N,K]^T  (fp32 in/out)
// CTA tile 128x128, BK=16, 256 threads (8 warps, 4x2), warp tile 32x64.
// Smem [row][k] with stride 20 -> conflict-free fragment loads.
// Double-buffered cp.async. M=4096, N=1024, K=1024 (all divisible).
// ---------------------------------------------------------------------------
#define BM 128
#define BN 128
#define BK 16
#define KSTRIDE 20

__global__ void __launch_bounds__(256) gemm_tc(const float* __restrict__ A,
                                               const float* __restrict__ B,
                                               float* __restrict__ C,
                                               int M, int N, int K)
{
    __shared__ float As[2][BM][KSTRIDE];
    __shared__ float Bs[2][BN][KSTRIDE];

    const int tid  = threadIdx.x;
    const int wid  = tid >> 5;
    const int lane = tid & 31;
    const int g    = lane >> 2;   // 0..7
    const int t    = lane & 3;    // 0..3
    const int wm   = wid >> 1;    // 0..3 (M)
    const int wn   = wid & 1;     // 0..1 (N)
    const int row0 = blockIdx.y * BM;
    const int col0 = blockIdx.x * BN;

    const float* Ab = A + (size_t)row0 * K;
    const float* Bb = B + (size_t)col0 * K;

    float acc[2][8][4];
    #pragma unroll
    for (int i = 0; i < 2; i++)
        #pragma unroll
        for (int j = 0; j < 8; j++)
            #pragma unroll
            for (int r = 0; r < 4; r++) acc[i][j][r] = 0.f;

    const int lm = tid >> 2;          // 0..63
    const int lc = (tid & 3) * 4;     // 0,4,8,12

    auto load_tile = [&](int kc, int s) {
        const float* ag = Ab + kc * BK;
        const float* bg = Bb + kc * BK;
        #pragma unroll
        for (int i = 0; i < 2; i++) {
            const int r = lm + i * 64;
            cp_async16(smem_u32(&As[s][r][lc]), ag + (size_t)r * K + lc);
            cp_async16(smem_u32(&Bs[s][r][lc]), bg + (size_t)r * K + lc);
        }
        CP_COMMIT();
    };

    const int NCH = K / BK;   // 64
    load_tile(0, 0);
    int buf = 0;

    for (int kc = 0; kc < NCH; kc++) {
        if (kc + 1 < NCH) {
            load_tile(kc + 1, buf ^ 1);
            CP_WAIT(1);
        } else {
            CP_WAIT(0);
        }
        __syncthreads();

        #pragma unroll
        for (int ks = 0; ks < 2; ks++) {
            const int kb = ks * 8;
            uint32_t af[2][4], bf[8][2];
            #pragma unroll
            for (int i = 0; i < 2; i++) {
                const int m = wm * 32 + i * 16 + g;
                af[i][0] = f2tf32(As[buf][m    ][kb + t]);
                af[i][1] = f2tf32(As[buf][m + 8][kb + t]);
                af[i][2] = f2tf32(As[buf][m    ][kb + t + 4]);
                af[i][3] = f2tf32(As[buf][m + 8][kb + t + 4]);
            }
            #pragma unroll
            for (int j = 0; j < 8; j++) {
                const int n = wn * 64 + j * 8 + g;
                bf[j][0] = f2tf32(Bs[buf][n][kb + t]);
                bf[j][1] = f2tf32(Bs[buf][n][kb + t + 4]);
            }
            #pragma unroll
            for (int i = 0; i < 2; i++)
                #pragma unroll
                for (int j = 0; j < 8; j++)
                    mma_tf32(acc[i][j], af[i], bf[j]);
        }
        __syncthreads();
        buf ^= 1;
    }

    // Epilogue: c0,c1 -> (m, 2t..2t+1), c2,c3 -> (m+8, same cols)
    #pragma unroll
    for (int i = 0; i < 2; i++) {
        #pragma unroll
        for (int j = 0; j < 8; j++) {
            const int m = row0 + wm * 32 + i * 16 + g;
            const int n = col0 + wn * 64 + j * 8 + 2 * t;
            *(float2*)&C[(size_t)m * N + n]       = make_float2(acc[i][j][0], acc[i][j][1]);
            *(float2*)&C[(size_t)(m + 8) * N + n] = make_float2(acc[i][j][2], acc[i][j][3]);
        }
    }
}

// ---------------------------------------------------------------------------
// Causal flash attention (SIMT fp32). q/k/v/o are [B,S,D] with head h at
// columns [h*64, h*64+64). Grid (S/128, B*H), 128 threads, 1 query each.
// ---------------------------------------------------------------------------
__global__ void __launch_bounds__(128) attn_kernel(const float* __restrict__ qg,
                                                   const float* __restrict__ kg,
                                                   const float* __restrict__ vg,
                                                   float* __restrict__ og)
{
    const int bh = blockIdx.y;
    const int b  = bh >> 4;
    const int h  = bh & 15;
    const int q0 = blockIdx.x * 128;
    const int t  = threadIdx.x;
    const int qi = q0 + t;

    __shared__ float4 Ks[32][16];
    __shared__ float4 Vs[32][16];

    float4 qr[16];
    const float4* qp = (const float4*)(qg + ((size_t)(b * CS + qi)) * CD + h * CDK);
    #pragma unroll
    for (int i = 0; i < 16; i++) qr[i] = qp[i];

    float4 acc[16];
    #pragma unroll
    for (int i = 0; i < 16; i++) acc[i] = make_float4(0.f, 0.f, 0.f, 0.f);
    float m = -1e30f, l = 0.f;

    const int lr = t >> 2;
    const int lc = t & 3;
    const int ntiles = q0 / 32 + 4;

    for (int kt = 0; kt < ntiles; kt++) {
        const int k0 = kt * 32;
        const float4* kp = (const float4*)(kg + ((size_t)(b * CS + k0 + lr)) * CD + h * CDK);
        const float4* vp = (const float4*)(vg + ((size_t)(b * CS + k0 + lr)) * CD + h * CDK);
        #pragma unroll
        for (int j = 0; j < 4; j++) {
            Ks[lr][lc * 4 + j] = kp[lc * 4 + j];
            Vs[lr][lc * 4 + j] = vp[lc * 4 + j];
        }
        __syncthreads();

        float sc[32];
        #pragma unroll
        for (int j = 0; j < 32; j++) {
            float sx = 0.f, sy = 0.f, sz = 0.f, sw = 0.f;
            #pragma unroll
            for (int d = 0; d < 16; d++) {
                float4 kk = Ks[j][d];
                sx = fmaf(qr[d].x, kk.x, sx);
                sy = fmaf(qr[d].y, kk.y, sy);
                sz = fmaf(qr[d].z, kk.z, sz);
                sw = fmaf(qr[d].w, kk.w, sw);
            }
            float s = ((sx + sy) + (sz + sw)) * 0.125f;
            sc[j] = (k0 + j > qi) ? -1e30f : s;
        }

        float mt = m;
        #pragma unroll
        for (int j = 0; j < 32; j++) mt = fmaxf(mt, sc[j]);
        float corr = __expf(m - mt);
        l *= corr;
        #pragma unroll
        for (int i = 0; i < 16; i++) {
            acc[i].x *= corr; acc[i].y *= corr;
            acc[i].z *= corr; acc[i].w *= corr;
        }
        #pragma unroll
        for (int j = 0; j < 32; j++) {
            float p = __expf(sc[j] - mt);
            l += p;
            #pragma unroll
            for (int d = 0; d < 16; d++) {
                float4 vv = Vs[j][d];
                acc[d].x = fmaf(p, vv.x, acc[d].x);
                acc[d].y = fmaf(p, vv.y, acc[d].y);
                acc[d].z = fmaf(p, vv.z, acc[d].z);
                acc[d].w = fmaf(p, vv.w, acc[d].w);
            }
        }
        m = mt;
        __syncthreads();
    }

    const float inv = 1.0f / l;
    float4* op = (float4*)(og + ((size_t)(b * CS + qi)) * CD + h * CDK);
    #pragma unroll
    for (int i = 0; i < 16; i++)
        op[i] = make_float4(acc[i].x * inv, acc[i].y * inv, acc[i].z * inv, acc[i].w * inv);
}

// ---------------------------------------------------------------------------
// Launch. Inputs: Q, K, V, mask(ignored), w_q, w_k, w_v, w_o. Out: [B,S,D] f32
// ---------------------------------------------------------------------------
extern "C" void kernel_launch(void* const* d_in, const int* in_sizes, int n_in,
                              void* d_out, int out_size)
{
    const float* Q  = (const float*)d_in[0];
    const float* K  = (const float*)d_in[1];
    const float* V  = (const float*)d_in[2];
    const float* wq = (const float*)d_in[4];
    const float* wk = (const float*)d_in[5];
    const float* wv = (const float*)d_in[6];
    const float* wo = (const float*)d_in[7];
    float* out = (float*)d_out;

    float *qb, *kb, *vb, *ab;
    cudaGetSymbolAddress((void**)&qb, g_q);
    cudaGetSymbolAddress((void**)&kb, g_k);
    cudaGetSymbolAddress((void**)&vb, g_v);
    cudaGetSymbolAddress((void**)&ab, g_a);

    dim3 gg(CD / BN, CM / BM);   // (8, 32)
    gemm_tc<<<gg, 256>>>(Q, wq, qb, CM, CD, CD);
    gemm_tc<<<gg, 256>>>(K, wk, kb, CM, CD, CD);
    gemm_tc<<<gg, 256>>>(V, wv, vb, CM, CD, CD);

    attn_kernel<<<dim3(CS / 128, CB * CH), 128>>>(qb, kb, vb, ab);

    gemm_tc<<<gg, 256>>>(ab, wo, out, CM, CD, CD);
}

// round 5
// speedup vs baseline: 3.4526x; 2.5060x over previous
#include <cuda_runtime.h>
#include <cstdint>
#include <math.h>

// Problem constants
#define CB 2
#define CS 2048
#define CD 1024
#define CH 16
#define CDK 64
#define CM (CB*CS)   // 4096 rows

// Scratch (device globals: allocation-free rule)
__device__ float g_q[CB*CS*CD];
__device__ float g_k[CB*CS*CD];
__device__ float g_v[CB*CS*CD];
__device__ float g_a[CB*CS*CD];

// ---------------------------------------------------------------------------
// Helpers
// ---------------------------------------------------------------------------
__device__ __forceinline__ uint32_t smem_u32(const void* p) {
    uint32_t a;
    asm("{ .reg .u64 t; cvta.to.shared.u64 t, %1; cvt.u32.u64 %0, t; }" : "=r"(a) : "l"(p));
    return a;
}
__device__ __forceinline__ void cp_async16(uint32_t dst, const void* src) {
    asm volatile("cp.async.cg.shared.global [%0], [%1], 16;" :: "r"(dst), "l"(src) : "memory");
}
#define CP_COMMIT() asm volatile("cp.async.commit_group;" ::: "memory")
#define CP_WAIT(n)  asm volatile("cp.async.wait_group %0;" :: "n"(n) : "memory")

__device__ __forceinline__ uint32_t f2tf32(float x) {
    uint32_t o;
    asm("cvt.rna.tf32.f32 %0, %1;" : "=r"(o) : "f"(x));
    return o;
}
__device__ __forceinline__ void mma_tf32(float c[4], const uint32_t a[4], const uint32_t b[2]) {
    asm volatile("mma.sync.aligned.m16n8k8.row.col.f32.tf32.tf32.f32 "
                 "{%0,%1,%2,%3}, {%4,%5,%6,%7}, {%8,%9}, {%0,%1,%2,%3};"
                 : "+f"(c[0]), "+f"(c[1]), "+f"(c[2]), "+f"(c[3])
                 : "r"(a[0]), "r"(a[1]), "r"(a[2]), "r"(a[3]), "r"(b[0]), "r"(b[1]));
}

// ---------------------------------------------------------------------------
// TF32 tensor-core GEMM: C[M,N] = A[M,K] * B[N,K]^T  (fp32 in/out)
// CTA tile 128x128, BK=16, 256 threads (8 warps, 4x2), warp tile 32x64.
// ---------------------------------------------------------------------------
#define BM 128
#define BN 128
#define BK 16
#define KSTRIDE 20

__global__ void __launch_bounds__(256) gemm_tc(const float* __restrict__ A,
                                               const float* __restrict__ B,
                                               float* __restrict__ C,
                                               int M, int N, int K)
{
    __shared__ float As[2][BM][KSTRIDE];
    __shared__ float Bs[2][BN][KSTRIDE];

    const int tid  = threadIdx.x;
    const int wid  = tid >> 5;
    const int lane = tid & 31;
    const int g    = lane >> 2;
    const int t    = lane & 3;
    const int wm   = wid >> 1;
    const int wn   = wid & 1;
    const int row0 = blockIdx.y * BM;
    const int col0 = blockIdx.x * BN;

    const float* Ab = A + (size_t)row0 * K;
    const float* Bb = B + (size_t)col0 * K;

    float acc[2][8][4];
    #pragma unroll
    for (int i = 0; i < 2; i++)
        #pragma unroll
        for (int j = 0; j < 8; j++)
            #pragma unroll
            for (int r = 0; r < 4; r++) acc[i][j][r] = 0.f;

    const int lm = tid >> 2;
    const int lc = (tid & 3) * 4;

    auto load_tile = [&](int kc, int s) {
        const float* ag = Ab + kc * BK;
        const float* bg = Bb + kc * BK;
        #pragma unroll
        for (int i = 0; i < 2; i++) {
            const int r = lm + i * 64;
            cp_async16(smem_u32(&As[s][r][lc]), ag + (size_t)r * K + lc);
            cp_async16(smem_u32(&Bs[s][r][lc]), bg + (size_t)r * K + lc);
        }
        CP_COMMIT();
    };

    const int NCH = K / BK;
    load_tile(0, 0);
    int buf = 0;

    for (int kc = 0; kc < NCH; kc++) {
        if (kc + 1 < NCH) {
            load_tile(kc + 1, buf ^ 1);
            CP_WAIT(1);
        } else {
            CP_WAIT(0);
        }
        __syncthreads();

        #pragma unroll
        for (int ks = 0; ks < 2; ks++) {
            const int kb = ks * 8;
            uint32_t af[2][4], bf[8][2];
            #pragma unroll
            for (int i = 0; i < 2; i++) {
                const int m = wm * 32 + i * 16 + g;
                af[i][0] = f2tf32(As[buf][m    ][kb + t]);
                af[i][1] = f2tf32(As[buf][m + 8][kb + t]);
                af[i][2] = f2tf32(As[buf][m    ][kb + t + 4]);
                af[i][3] = f2tf32(As[buf][m + 8][kb + t + 4]);
            }
            #pragma unroll
            for (int j = 0; j < 8; j++) {
                const int n = wn * 64 + j * 8 + g;
                bf[j][0] = f2tf32(Bs[buf][n][kb + t]);
                bf[j][1] = f2tf32(Bs[buf][n][kb + t + 4]);
            }
            #pragma unroll
            for (int i = 0; i < 2; i++)
                #pragma unroll
                for (int j = 0; j < 8; j++)
                    mma_tf32(acc[i][j], af[i], bf[j]);
        }
        __syncthreads();
        buf ^= 1;
    }

    #pragma unroll
    for (int i = 0; i < 2; i++) {
        #pragma unroll
        for (int j = 0; j < 8; j++) {
            const int m = row0 + wm * 32 + i * 16 + g;
            const int n = col0 + wn * 64 + j * 8 + 2 * t;
            *(float2*)&C[(size_t)m * N + n]       = make_float2(acc[i][j][0], acc[i][j][1]);
            *(float2*)&C[(size_t)(m + 8) * N + n] = make_float2(acc[i][j][2], acc[i][j][3]);
        }
    }
}

// ---------------------------------------------------------------------------
// Tensor-core causal flash attention (tf32 mma.sync).
// CTA: one (b,h), 128 queries. 4 warps x 32-query warp tile. 64-key tiles.
// Smem (u32 tf32 bits): Qs[128][72], Ks[64][72], Vs[64][72], Ps[128][72].
// Stride 72 floats -> conflict-free fragment loads (8g+t / 8t+g patterns).
// ---------------------------------------------------------------------------
#define ASTRIDE 72
#define ASMEM ((128 + 64 + 64 + 128) * ASTRIDE * 4)   // 110592 bytes

__global__ void __launch_bounds__(128) attn_tc(const float* __restrict__ qg,
                                               const float* __restrict__ kg,
                                               const float* __restrict__ vg,
                                               float* __restrict__ og)
{
    extern __shared__ uint32_t sm[];
    uint32_t* Qs = sm;                       // [128][72]
    uint32_t* Ks = sm + 128 * ASTRIDE;       // [64][72]
    uint32_t* Vs = Ks + 64 * ASTRIDE;        // [64][72]
    uint32_t* Ps = Vs + 64 * ASTRIDE;        // [128][72]

    const int bh = blockIdx.y;
    const int b  = bh >> 4;
    const int h  = bh & 15;
    const int q0 = (gridDim.x - 1 - blockIdx.x) * 128;   // longest CTAs first
    const int tid = threadIdx.x;
    const int w = tid >> 5, lane = tid & 31;
    const int g = lane >> 2, t = lane & 3;

    // Stage Q (pre-converted to tf32)
    const float* qbase = qg + ((size_t)(b * CS + q0)) * CD + h * CDK;
    #pragma unroll
    for (int i = 0; i < 16; i++) {
        int idx = tid + i * 128;
        int r = idx >> 4, c4 = (idx & 15) << 2;
        float4 v = *(const float4*)(qbase + (size_t)r * CD + c4);
        Qs[r * ASTRIDE + c4 + 0] = f2tf32(v.x);
        Qs[r * ASTRIDE + c4 + 1] = f2tf32(v.y);
        Qs[r * ASTRIDE + c4 + 2] = f2tf32(v.z);
        Qs[r * ASTRIDE + c4 + 3] = f2tf32(v.w);
    }

    float o[2][8][4];
    #pragma unroll
    for (int mt = 0; mt < 2; mt++)
        #pragma unroll
        for (int nt = 0; nt < 8; nt++)
            #pragma unroll
            for (int c = 0; c < 4; c++) o[mt][nt][c] = 0.f;
    float mrow[2][2] = {{-1e30f, -1e30f}, {-1e30f, -1e30f}};
    float lrow[2][2] = {{0.f, 0.f}, {0.f, 0.f}};

    const float* kbase = kg + ((size_t)(b * CS)) * CD + h * CDK;
    const float* vbase = vg + ((size_t)(b * CS)) * CD + h * CDK;
    const int ntiles = q0 / 64 + 2;

    __syncthreads();

    for (int kt = 0; kt < ntiles; kt++) {
        const int k0 = kt * 64;
        // Stage K and V tiles (tf32)
        #pragma unroll
        for (int i = 0; i < 8; i++) {
            int idx = tid + i * 128;
            int r = idx >> 4, c4 = (idx & 15) << 2;
            float4 kv = *(const float4*)(kbase + (size_t)(k0 + r) * CD + c4);
            float4 vv = *(const float4*)(vbase + (size_t)(k0 + r) * CD + c4);
            Ks[r * ASTRIDE + c4 + 0] = f2tf32(kv.x);
            Ks[r * ASTRIDE + c4 + 1] = f2tf32(kv.y);
            Ks[r * ASTRIDE + c4 + 2] = f2tf32(kv.z);
            Ks[r * ASTRIDE + c4 + 3] = f2tf32(kv.w);
            Vs[r * ASTRIDE + c4 + 0] = f2tf32(vv.x);
            Vs[r * ASTRIDE + c4 + 1] = f2tf32(vv.y);
            Vs[r * ASTRIDE + c4 + 2] = f2tf32(vv.z);
            Vs[r * ASTRIDE + c4 + 3] = f2tf32(vv.w);
        }
        __syncthreads();

        // Warp-level skip: all keys of this tile above all of this warp's rows
        if (k0 <= q0 + 32 * w + 31) {
            // S = Q * K^T
            float s[2][8][4];
            #pragma unroll
            for (int mt = 0; mt < 2; mt++)
                #pragma unroll
                for (int nt = 0; nt < 8; nt++)
                    #pragma unroll
                    for (int c = 0; c < 4; c++) s[mt][nt][c] = 0.f;

            #pragma unroll
            for (int kc = 0; kc < 8; kc++) {
                uint32_t bf[8][2];
                #pragma unroll
                for (int nt = 0; nt < 8; nt++) {
                    bf[nt][0] = Ks[(8 * nt + g) * ASTRIDE + 8 * kc + t];
                    bf[nt][1] = Ks[(8 * nt + g) * ASTRIDE + 8 * kc + t + 4];
                }
                #pragma unroll
                for (int mt = 0; mt < 2; mt++) {
                    const int mr = 32 * w + 16 * mt;
                    uint32_t af[4];
                    af[0] = Qs[(mr + g)     * ASTRIDE + 8 * kc + t];
                    af[1] = Qs[(mr + g + 8) * ASTRIDE + 8 * kc + t];
                    af[2] = Qs[(mr + g)     * ASTRIDE + 8 * kc + t + 4];
                    af[3] = Qs[(mr + g + 8) * ASTRIDE + 8 * kc + t + 4];
                    #pragma unroll
                    for (int nt = 0; nt < 8; nt++)
                        mma_tf32(s[mt][nt], af, bf[nt]);
                }
            }

            // scale + causal mask (only diagonal tiles need it)
            const bool needmask = (k0 + 63) > (q0 + 32 * w);
            #pragma unroll
            for (int mt = 0; mt < 2; mt++)
                #pragma unroll
                for (int nt = 0; nt < 8; nt++)
                    #pragma unroll
                    for (int c = 0; c < 4; c++) {
                        float sv = s[mt][nt][c] * 0.125f;
                        if (needmask) {
                            int key = k0 + 8 * nt + 2 * t + (c & 1);
                            int qr  = q0 + 32 * w + 16 * mt + 8 * (c >> 1) + g;
                            if (key > qr) sv = -1e30f;
                        }
                        s[mt][nt][c] = sv;
                    }

            // online softmax (rows split across the t-quad)
            #pragma unroll
            for (int mt = 0; mt < 2; mt++)
                #pragma unroll
                for (int p = 0; p < 2; p++) {
                    float mx = -1e30f;
                    #pragma unroll
                    for (int nt = 0; nt < 8; nt++) {
                        mx = fmaxf(mx, s[mt][nt][2 * p]);
                        mx = fmaxf(mx, s[mt][nt][2 * p + 1]);
                    }
                    mx = fmaxf(mx, __shfl_xor_sync(0xffffffffu, mx, 1));
                    mx = fmaxf(mx, __shfl_xor_sync(0xffffffffu, mx, 2));
                    const float mnew = fmaxf(mrow[mt][p], mx);
                    const float corr = __expf(mrow[mt][p] - mnew);
                    mrow[mt][p] = mnew;
                    float ls = 0.f;
                    #pragma unroll
                    for (int nt = 0; nt < 8; nt++) {
                        float p0 = __expf(s[mt][nt][2 * p]     - mnew);
                        float p1 = __expf(s[mt][nt][2 * p + 1] - mnew);
                        s[mt][nt][2 * p]     = p0;
                        s[mt][nt][2 * p + 1] = p1;
                        ls += p0 + p1;
                        o[mt][nt][2 * p]     *= corr;
                        o[mt][nt][2 * p + 1] *= corr;
                    }
                    lrow[mt][p] = lrow[mt][p] * corr + ls;
                }

            // P -> smem (C-fragment layout -> A-fragment layout)
            #pragma unroll
            for (int mt = 0; mt < 2; mt++)
                #pragma unroll
                for (int p = 0; p < 2; p++) {
                    const int row = 32 * w + 16 * mt + 8 * p + g;
                    #pragma unroll
                    for (int nt = 0; nt < 8; nt++) {
                        uint2 pv = make_uint2(f2tf32(s[mt][nt][2 * p]),
                                              f2tf32(s[mt][nt][2 * p + 1]));
                        *(uint2*)&Ps[row * ASTRIDE + 8 * nt + 2 * t] = pv;
                    }
                }
            __syncwarp();

            // O += P * V   (V read transposed directly from smem)
            #pragma unroll
            for (int kc = 0; kc < 8; kc++) {
                uint32_t bf[8][2];
                #pragma unroll
                for (int nt = 0; nt < 8; nt++) {
                    bf[nt][0] = Vs[(8 * kc + t)     * ASTRIDE + 8 * nt + g];
                    bf[nt][1] = Vs[(8 * kc + t + 4) * ASTRIDE + 8 * nt + g];
                }
                #pragma unroll
                for (int mt = 0; mt < 2; mt++) {
                    const int mr = 32 * w + 16 * mt;
                    uint32_t af[4];
                    af[0] = Ps[(mr + g)     * ASTRIDE + 8 * kc + t];
                    af[1] = Ps[(mr + g + 8) * ASTRIDE + 8 * kc + t];
                    af[2] = Ps[(mr + g)     * ASTRIDE + 8 * kc + t + 4];
                    af[3] = Ps[(mr + g + 8) * ASTRIDE + 8 * kc + t + 4];
                    #pragma unroll
                    for (int nt = 0; nt < 8; nt++)
                        mma_tf32(o[mt][nt], af, bf[nt]);
                }
            }
        }
        __syncthreads();
    }

    // finalize: reduce l across the quad, normalize, store
    float inv[2][2];
    #pragma unroll
    for (int mt = 0; mt < 2; mt++)
        #pragma unroll
        for (int p = 0; p < 2; p++) {
            float lr = lrow[mt][p];
            lr += __shfl_xor_sync(0xffffffffu, lr, 1);
            lr += __shfl_xor_sync(0xffffffffu, lr, 2);
            inv[mt][p] = 1.f / lr;
        }

    float* obase = og + ((size_t)(b * CS + q0)) * CD + h * CDK;
    #pragma unroll
    for (int mt = 0; mt < 2; mt++)
        #pragma unroll
        for (int nt = 0; nt < 8; nt++) {
            const int r0 = 32 * w + 16 * mt + g;
            *(float2*)(obase + (size_t)r0 * CD + 8 * nt + 2 * t) =
                make_float2(o[mt][nt][0] * inv[mt][0], o[mt][nt][1] * inv[mt][0]);
            *(float2*)(obase + (size_t)(r0 + 8) * CD + 8 * nt + 2 * t) =
                make_float2(o[mt][nt][2] * inv[mt][1], o[mt][nt][3] * inv[mt][1]);
        }
}

// ---------------------------------------------------------------------------
// Launch. Inputs: Q, K, V, mask(ignored), w_q, w_k, w_v, w_o. Out: [B,S,D] f32
// ---------------------------------------------------------------------------
extern "C" void kernel_launch(void* const* d_in, const int* in_sizes, int n_in,
                              void* d_out, int out_size)
{
    const float* Q  = (const float*)d_in[0];
    const float* K  = (const float*)d_in[1];
    const float* V  = (const float*)d_in[2];
    const float* wq = (const float*)d_in[4];
    const float* wk = (const float*)d_in[5];
    const float* wv = (const float*)d_in[6];
    const float* wo = (const float*)d_in[7];
    float* out = (float*)d_out;

    float *qb, *kb, *vb, *ab;
    cudaGetSymbolAddress((void**)&qb, g_q);
    cudaGetSymbolAddress((void**)&kb, g_k);
    cudaGetSymbolAddress((void**)&vb, g_v);
    cudaGetSymbolAddress((void**)&ab, g_a);

    static bool attr_set = false;
    if (!attr_set) {
        cudaFuncSetAttribute(attn_tc, cudaFuncAttributeMaxDynamicSharedMemorySize, ASMEM);
        attr_set = true;
    }

    dim3 gg(CD / BN, CM / BM);   // (8, 32)
    gemm_tc<<<gg, 256>>>(Q, wq, qb, CM, CD, CD);
    gemm_tc<<<gg, 256>>>(K, wk, kb, CM, CD, CD);
    gemm_tc<<<gg, 256>>>(V, wv, vb, CM, CD, CD);

    attn_tc<<<dim3(CS / 128, CB * CH), 128, ASMEM>>>(qb, kb, vb, ab);

    gemm_tc<<<gg, 256>>>(ab, wo, out, CM, CD, CD);
}

// round 6
// speedup vs baseline: 3.6224x; 1.0492x over previous
#include <cuda_runtime.h>
#include <cstdint>
#include <math.h>

// Problem constants
#define CB 2
#define CS 2048
#define CD 1024
#define CH 16
#define CDK 64
#define CM (CB*CS)   // 4096 rows

// Scratch (device globals: allocation-free rule)
__device__ float g_q[CB*CS*CD];
__device__ float g_k[CB*CS*CD];
__device__ float g_v[CB*CS*CD];
__device__ float g_a[CB*CS*CD];

// ---------------------------------------------------------------------------
// Helpers
// ---------------------------------------------------------------------------
__device__ __forceinline__ uint32_t smem_u32(const void* p) {
    uint32_t a;
    asm("{ .reg .u64 t; cvta.to.shared.u64 t, %1; cvt.u32.u64 %0, t; }" : "=r"(a) : "l"(p));
    return a;
}
__device__ __forceinline__ void cp_async16(uint32_t dst, const void* src) {
    asm volatile("cp.async.cg.shared.global [%0], [%1], 16;" :: "r"(dst), "l"(src) : "memory");
}
#define CP_COMMIT() asm volatile("cp.async.commit_group;" ::: "memory")
#define CP_WAIT(n)  asm volatile("cp.async.wait_group %0;" :: "n"(n) : "memory")

__device__ __forceinline__ uint32_t f2tf32(float x) {
    uint32_t o;
    asm("cvt.rna.tf32.f32 %0, %1;" : "=r"(o) : "f"(x));
    return o;
}
__device__ __forceinline__ void mma_tf32(float c[4], const uint32_t a[4], const uint32_t b[2]) {
    asm volatile("mma.sync.aligned.m16n8k8.row.col.f32.tf32.tf32.f32 "
                 "{%0,%1,%2,%3}, {%4,%5,%6,%7}, {%8,%9}, {%0,%1,%2,%3};"
                 : "+f"(c[0]), "+f"(c[1]), "+f"(c[2]), "+f"(c[3])
                 : "r"(a[0]), "r"(a[1]), "r"(a[2]), "r"(a[3]), "r"(b[0]), "r"(b[1]));
}

// ---------------------------------------------------------------------------
// TF32 tensor-core GEMM: C[M,N] = A[M,K] * B[N,K]^T  (fp32 in/out)
// CTA tile 128x128, BK=16, 256 threads (8 warps, 4x2), warp tile 32x64.
// ---------------------------------------------------------------------------
#define BM 128
#define BN 128
#define BK 16
#define KSTRIDE 20

__global__ void __launch_bounds__(256) gemm_tc(const float* __restrict__ A,
                                               const float* __restrict__ B,
                                               float* __restrict__ C,
                                               int M, int N, int K)
{
    __shared__ float As[2][BM][KSTRIDE];
    __shared__ float Bs[2][BN][KSTRIDE];

    const int tid  = threadIdx.x;
    const int wid  = tid >> 5;
    const int lane = tid & 31;
    const int g    = lane >> 2;
    const int t    = lane & 3;
    const int wm   = wid >> 1;
    const int wn   = wid & 1;
    const int row0 = blockIdx.y * BM;
    const int col0 = blockIdx.x * BN;

    const float* Ab = A + (size_t)row0 * K;
    const float* Bb = B + (size_t)col0 * K;

    float acc[2][8][4];
    #pragma unroll
    for (int i = 0; i < 2; i++)
        #pragma unroll
        for (int j = 0; j < 8; j++)
            #pragma unroll
            for (int r = 0; r < 4; r++) acc[i][j][r] = 0.f;

    const int lm = tid >> 2;
    const int lc = (tid & 3) * 4;

    auto load_tile = [&](int kc, int s) {
        const float* ag = Ab + kc * BK;
        const float* bg = Bb + kc * BK;
        #pragma unroll
        for (int i = 0; i < 2; i++) {
            const int r = lm + i * 64;
            cp_async16(smem_u32(&As[s][r][lc]), ag + (size_t)r * K + lc);
            cp_async16(smem_u32(&Bs[s][r][lc]), bg + (size_t)r * K + lc);
        }
        CP_COMMIT();
    };

    const int NCH = K / BK;
    load_tile(0, 0);
    int buf = 0;

    for (int kc = 0; kc < NCH; kc++) {
        if (kc + 1 < NCH) {
            load_tile(kc + 1, buf ^ 1);
            CP_WAIT(1);
        } else {
            CP_WAIT(0);
        }
        __syncthreads();

        #pragma unroll
        for (int ks = 0; ks < 2; ks++) {
            const int kb = ks * 8;
            uint32_t af[2][4], bf[8][2];
            #pragma unroll
            for (int i = 0; i < 2; i++) {
                const int m = wm * 32 + i * 16 + g;
                af[i][0] = f2tf32(As[buf][m    ][kb + t]);
                af[i][1] = f2tf32(As[buf][m + 8][kb + t]);
                af[i][2] = f2tf32(As[buf][m    ][kb + t + 4]);
                af[i][3] = f2tf32(As[buf][m + 8][kb + t + 4]);
            }
            #pragma unroll
            for (int j = 0; j < 8; j++) {
                const int n = wn * 64 + j * 8 + g;
                bf[j][0] = f2tf32(Bs[buf][n][kb + t]);
                bf[j][1] = f2tf32(Bs[buf][n][kb + t + 4]);
            }
            #pragma unroll
            for (int i = 0; i < 2; i++)
                #pragma unroll
                for (int j = 0; j < 8; j++)
                    mma_tf32(acc[i][j], af[i], bf[j]);
        }
        __syncthreads();
        buf ^= 1;
    }

    #pragma unroll
    for (int i = 0; i < 2; i++) {
        #pragma unroll
        for (int j = 0; j < 8; j++) {
            const int m = row0 + wm * 32 + i * 16 + g;
            const int n = col0 + wn * 64 + j * 8 + 2 * t;
            *(float2*)&C[(size_t)m * N + n]       = make_float2(acc[i][j][0], acc[i][j][1]);
            *(float2*)&C[(size_t)(m + 8) * N + n] = make_float2(acc[i][j][2], acc[i][j][3]);
        }
    }
}

// ---------------------------------------------------------------------------
// Tensor-core causal flash attention v2 (tf32 mma.sync).
// CTA: one (b,h) x 128 queries, 4 warps x 32-query warp tiles.
// 32-key K/V stages, cp.async double-buffered, raw fp32 K/V (HMMA truncates).
// Strides: Q/K/P = 68 words ((4g+t)%32 conflict-free), V = 72 ((8t+g)%32).
// Smem 103KB -> 2 CTAs/SM.
// ---------------------------------------------------------------------------
#define QST 68
#define KST 68
#define VST 72
#define PST 68
#define KT  32   // keys per stage

#define OFF_Q 0
#define OFF_K (128 * QST)                 // 8704
#define OFF_V (OFF_K + 2 * KT * KST)      // + 4352
#define OFF_P (OFF_V + 2 * KT * VST)      // + 4608
#define AWORDS (OFF_P + 128 * PST)        // + 8704 = 26368
#define ASMEM (AWORDS * 4)                // 105472 bytes

__global__ void __launch_bounds__(128, 2) attn_tc(const float* __restrict__ qg,
                                                  const float* __restrict__ kg,
                                                  const float* __restrict__ vg,
                                                  float* __restrict__ og)
{
    extern __shared__ uint32_t sm[];
    uint32_t* Qs = sm + OFF_Q;
    uint32_t* Ksm = sm + OFF_K;
    uint32_t* Vsm = sm + OFF_V;
    uint32_t* Ps = sm + OFF_P;

    const int bh = blockIdx.y;
    const int b  = bh >> 4;
    const int h  = bh & 15;
    const int q0 = (gridDim.x - 1 - blockIdx.x) * 128;   // longest CTAs first
    const int tid = threadIdx.x;
    const int w = tid >> 5, lane = tid & 31;
    const int g = lane >> 2, t = lane & 3;

    const float* kbase = kg + ((size_t)(b * CS)) * CD + h * CDK;
    const float* vbase = vg + ((size_t)(b * CS)) * CD + h * CDK;

    // Stage Q (RNA tf32)
    const float* qbase = qg + ((size_t)(b * CS + q0)) * CD + h * CDK;
    #pragma unroll
    for (int i = 0; i < 16; i++) {
        int idx = tid + i * 128;
        int r = idx >> 4, c4 = (idx & 15) << 2;
        float4 v = *(const float4*)(qbase + (size_t)r * CD + c4);
        Qs[r * QST + c4 + 0] = f2tf32(v.x);
        Qs[r * QST + c4 + 1] = f2tf32(v.y);
        Qs[r * QST + c4 + 2] = f2tf32(v.z);
        Qs[r * QST + c4 + 3] = f2tf32(v.w);
    }

    // K/V stage loader: 32 rows x 256B each via cp.async (raw fp32)
    const uint32_t kb0 = smem_u32(Ksm);
    const uint32_t vb0 = smem_u32(Vsm);
    auto load_stage = [&](int kt_, int s) {
        const int k0 = kt_ * KT;
        const uint32_t kd = kb0 + s * (KT * KST * 4);
        const uint32_t vd = vb0 + s * (KT * VST * 4);
        #pragma unroll
        for (int i = 0; i < 4; i++) {
            int idx = tid + i * 128;
            int r = idx >> 4, c = idx & 15;
            cp_async16(kd + r * (KST * 4) + c * 16, kbase + (size_t)(k0 + r) * CD + c * 4);
        }
        #pragma unroll
        for (int i = 0; i < 4; i++) {
            int idx = tid + i * 128;
            int r = idx >> 4, c = idx & 15;
            cp_async16(vd + r * (VST * 4) + c * 16, vbase + (size_t)(k0 + r) * CD + c * 4);
        }
        CP_COMMIT();
    };

    float o[2][8][4];
    #pragma unroll
    for (int mt = 0; mt < 2; mt++)
        #pragma unroll
        for (int nt = 0; nt < 8; nt++)
            #pragma unroll
            for (int c = 0; c < 4; c++) o[mt][nt][c] = 0.f;
    float mrow[2][2] = {{-1e30f, -1e30f}, {-1e30f, -1e30f}};
    float lrow[2][2] = {{0.f, 0.f}, {0.f, 0.f}};

    const int ntiles = q0 / KT + 4;
    int buf = 0;
    load_stage(0, 0);

    for (int kt = 0; kt < ntiles; kt++) {
        const int k0 = kt * KT;
        if (kt + 1 < ntiles) {
            load_stage(kt + 1, buf ^ 1);
            CP_WAIT(1);
        } else {
            CP_WAIT(0);
        }
        __syncthreads();

        if (k0 <= q0 + 32 * w + 31) {
            const uint32_t* Kb = Ksm + buf * (KT * KST);
            const uint32_t* Vb = Vsm + buf * (KT * VST);

            // S = Q * K^T   (K raw fp32 bits -> HW tf32 truncation)
            float s[2][4][4];
            #pragma unroll
            for (int mt = 0; mt < 2; mt++)
                #pragma unroll
                for (int nt = 0; nt < 4; nt++)
                    #pragma unroll
                    for (int c = 0; c < 4; c++) s[mt][nt][c] = 0.f;

            #pragma unroll
            for (int kc = 0; kc < 8; kc++) {
                uint32_t bf[4][2];
                #pragma unroll
                for (int nt = 0; nt < 4; nt++) {
                    bf[nt][0] = Kb[(8 * nt + g) * KST + 8 * kc + t];
                    bf[nt][1] = Kb[(8 * nt + g) * KST + 8 * kc + t + 4];
                }
                #pragma unroll
                for (int mt = 0; mt < 2; mt++) {
                    const int mr = 32 * w + 16 * mt;
                    uint32_t af[4];
                    af[0] = Qs[(mr + g)     * QST + 8 * kc + t];
                    af[1] = Qs[(mr + g + 8) * QST + 8 * kc + t];
                    af[2] = Qs[(mr + g)     * QST + 8 * kc + t + 4];
                    af[3] = Qs[(mr + g + 8) * QST + 8 * kc + t + 4];
                    #pragma unroll
                    for (int nt = 0; nt < 4; nt++)
                        mma_tf32(s[mt][nt], af, bf[nt]);
                }
            }

            // scale + causal mask (diagonal stages only)
            const bool needmask = (k0 + KT - 1) > (q0 + 32 * w);
            #pragma unroll
            for (int mt = 0; mt < 2; mt++)
                #pragma unroll
                for (int nt = 0; nt < 4; nt++)
                    #pragma unroll
                    for (int c = 0; c < 4; c++) {
                        float sv = s[mt][nt][c] * 0.125f;
                        if (needmask) {
                            int key = k0 + 8 * nt + 2 * t + (c & 1);
                            int qr  = q0 + 32 * w + 16 * mt + 8 * (c >> 1) + g;
                            if (key > qr) sv = -1e30f;
                        }
                        s[mt][nt][c] = sv;
                    }

            // online softmax
            #pragma unroll
            for (int mt = 0; mt < 2; mt++)
                #pragma unroll
                for (int p = 0; p < 2; p++) {
                    float mx = -1e30f;
                    #pragma unroll
                    for (int nt = 0; nt < 4; nt++) {
                        mx = fmaxf(mx, s[mt][nt][2 * p]);
                        mx = fmaxf(mx, s[mt][nt][2 * p + 1]);
                    }
                    mx = fmaxf(mx, __shfl_xor_sync(0xffffffffu, mx, 1));
                    mx = fmaxf(mx, __shfl_xor_sync(0xffffffffu, mx, 2));
                    const float mnew = fmaxf(mrow[mt][p], mx);
                    const float corr = __expf(mrow[mt][p] - mnew);
                    mrow[mt][p] = mnew;
                    float ls = 0.f;
                    #pragma unroll
                    for (int nt = 0; nt < 4; nt++) {
                        float p0 = __expf(s[mt][nt][2 * p]     - mnew);
                        float p1 = __expf(s[mt][nt][2 * p + 1] - mnew);
                        s[mt][nt][2 * p]     = p0;
                        s[mt][nt][2 * p + 1] = p1;
                        ls += p0 + p1;
                        #pragma unroll
                        for (int ntt = 0; ntt < 2; ntt++) { }
                    }
                    #pragma unroll
                    for (int nt = 0; nt < 8; nt++) {
                        o[mt][nt][2 * p]     *= corr;
                        o[mt][nt][2 * p + 1] *= corr;
                    }
                    lrow[mt][p] = lrow[mt][p] * corr + ls;
                }

            // P -> smem (C-frag -> A-frag layout), RNA tf32
            #pragma unroll
            for (int mt = 0; mt < 2; mt++)
                #pragma unroll
                for (int p = 0; p < 2; p++) {
                    const int row = 32 * w + 16 * mt + 8 * p + g;
                    #pragma unroll
                    for (int nt = 0; nt < 4; nt++) {
                        uint2 pv = make_uint2(f2tf32(s[mt][nt][2 * p]),
                                              f2tf32(s[mt][nt][2 * p + 1]));
                        *(uint2*)&Ps[row * PST + 8 * nt + 2 * t] = pv;
                    }
                }
            __syncwarp();

            // O += P * V   (V transposed from smem, raw fp32 bits)
            #pragma unroll
            for (int kc = 0; kc < 4; kc++) {
                uint32_t bf[8][2];
                #pragma unroll
                for (int nt = 0; nt < 8; nt++) {
                    bf[nt][0] = Vb[(8 * kc + t)     * VST + 8 * nt + g];
                    bf[nt][1] = Vb[(8 * kc + t + 4) * VST + 8 * nt + g];
                }
                #pragma unroll
                for (int mt = 0; mt < 2; mt++) {
                    const int mr = 32 * w + 16 * mt;
                    uint32_t af[4];
                    af[0] = Ps[(mr + g)     * PST + 8 * kc + t];
                    af[1] = Ps[(mr + g + 8) * PST + 8 * kc + t];
                    af[2] = Ps[(mr + g)     * PST + 8 * kc + t + 4];
                    af[3] = Ps[(mr + g + 8) * PST + 8 * kc + t + 4];
                    #pragma unroll
                    for (int nt = 0; nt < 8; nt++)
                        mma_tf32(o[mt][nt], af, bf[nt]);
                }
            }
        }
        __syncthreads();
        buf ^= 1;
    }

    // finalize
    float inv[2][2];
    #pragma unroll
    for (int mt = 0; mt < 2; mt++)
        #pragma unroll
        for (int p = 0; p < 2; p++) {
            float lr = lrow[mt][p];
            lr += __shfl_xor_sync(0xffffffffu, lr, 1);
            lr += __shfl_xor_sync(0xffffffffu, lr, 2);
            inv[mt][p] = 1.f / lr;
        }

    float* obase = og + ((size_t)(b * CS + q0)) * CD + h * CDK;
    #pragma unroll
    for (int mt = 0; mt < 2; mt++)
        #pragma unroll
        for (int nt = 0; nt < 8; nt++) {
            const int r0 = 32 * w + 16 * mt + g;
            *(float2*)(obase + (size_t)r0 * CD + 8 * nt + 2 * t) =
                make_float2(o[mt][nt][0] * inv[mt][0], o[mt][nt][1] * inv[mt][0]);
            *(float2*)(obase + (size_t)(r0 + 8) * CD + 8 * nt + 2 * t) =
                make_float2(o[mt][nt][2] * inv[mt][1], o[mt][nt][3] * inv[mt][1]);
        }
}

// ---------------------------------------------------------------------------
// Launch. Inputs: Q, K, V, mask(ignored), w_q, w_k, w_v, w_o. Out: [B,S,D] f32
// ---------------------------------------------------------------------------
extern "C" void kernel_launch(void* const* d_in, const int* in_sizes, int n_in,
                              void* d_out, int out_size)
{
    const float* Q  = (const float*)d_in[0];
    const float* K  = (const float*)d_in[1];
    const float* V  = (const float*)d_in[2];
    const float* wq = (const float*)d_in[4];
    const float* wk = (const float*)d_in[5];
    const float* wv = (const float*)d_in[6];
    const float* wo = (const float*)d_in[7];
    float* out = (float*)d_out;

    float *qb, *kb, *vb, *ab;
    cudaGetSymbolAddress((void**)&qb, g_q);
    cudaGetSymbolAddress((void**)&kb, g_k);
    cudaGetSymbolAddress((void**)&vb, g_v);
    cudaGetSymbolAddress((void**)&ab, g_a);

    static bool attr_set = false;
    if (!attr_set) {
        cudaFuncSetAttribute(attn_tc, cudaFuncAttributeMaxDynamicSharedMemorySize, ASMEM);
        attr_set = true;
    }

    dim3 gg(CD / BN, CM / BM);   // (8, 32)
    gemm_tc<<<gg, 256>>>(Q, wq, qb, CM, CD, CD);
    gemm_tc<<<gg, 256>>>(K, wk, kb, CM, CD, CD);
    gemm_tc<<<gg, 256>>>(V, wv, vb, CM, CD, CD);

    attn_tc<<<dim3(CS / 128, CB * CH), 128, ASMEM>>>(qb, kb, vb, ab);

    gemm_tc<<<gg, 256>>>(ab, wo, out, CM, CD, CD);
}

// round 9
// speedup vs baseline: 3.8205x; 1.0547x over previous
#include <cuda_runtime.h>
#include <cstdint>
#include <math.h>

// Problem constants
#define CB 2
#define CS 2048
#define CD 1024
#define CH 16
#define CDK 64
#define CM (CB*CS)   // 4096 rows

// Scratch (device globals: allocation-free rule)
__device__ float g_q[CB*CS*CD];
__device__ float g_k[CB*CS*CD];
__device__ float g_v[CB*CS*CD];
__device__ float g_a[CB*CS*CD];

// ---------------------------------------------------------------------------
// Helpers
// ---------------------------------------------------------------------------
__device__ __forceinline__ uint32_t smem_u32(const void* p) {
    uint32_t a;
    asm("{ .reg .u64 t; cvta.to.shared.u64 t, %1; cvt.u32.u64 %0, t; }" : "=r"(a) : "l"(p));
    return a;
}
__device__ __forceinline__ void cp_async16(uint32_t dst, const void* src) {
    asm volatile("cp.async.cg.shared.global [%0], [%1], 16;" :: "r"(dst), "l"(src) : "memory");
}
#define CP_COMMIT() asm volatile("cp.async.commit_group;" ::: "memory")
#define CP_WAIT(n)  asm volatile("cp.async.wait_group %0;" :: "n"(n) : "memory")

__device__ __forceinline__ uint32_t f2tf32(float x) {
    uint32_t o;
    asm("cvt.rna.tf32.f32 %0, %1;" : "=r"(o) : "f"(x));
    return o;
}
__device__ __forceinline__ void mma_tf32(float c[4], const uint32_t a[4], const uint32_t b[2]) {
    asm volatile("mma.sync.aligned.m16n8k8.row.col.f32.tf32.tf32.f32 "
                 "{%0,%1,%2,%3}, {%4,%5,%6,%7}, {%8,%9}, {%0,%1,%2,%3};"
                 : "+f"(c[0]), "+f"(c[1]), "+f"(c[2]), "+f"(c[3])
                 : "r"(a[0]), "r"(a[1]), "r"(a[2]), "r"(a[3]), "r"(b[0]), "r"(b[1]));
}

// Single dynamic smem symbol shared by both kernels (avoids conflicting
// extern __shared__ types in one TU).
extern __shared__ char dynsmem[];

// ---------------------------------------------------------------------------
// TF32 tensor-core GEMM v2: C[M,N] = A[M,K] * B[N,K]^T  (fp32 in/out)
// CTA tile 128x256, BK=16, 256 threads (8 warps = 2Mx4N), warp tile 64x64.
// Grid (N/256, M/128) = (4, 32) = 128 CTAs -> single wave on 148 SMs.
// Smem stride 20 words -> conflict-free fragment loads. Double buffered.
// ---------------------------------------------------------------------------
#define BM 128
#define BN 256
#define BK 16
#define KSTRIDE 20
#define AW (BM * KSTRIDE)        // 2560 words per A buffer
#define BW (BN * KSTRIDE)        // 5120 words per B buffer
#define GSMEM2 ((2 * AW + 2 * BW) * 4)   // 61440 bytes

__global__ void __launch_bounds__(256, 1) gemm_tc(const float* __restrict__ A,
                                                  const float* __restrict__ B,
                                                  float* __restrict__ C,
                                                  int M, int N, int K)
{
    float* smf = (float*)dynsmem;
    float* Asf = smf;             // [2][128][20]
    float* Bsf = smf + 2 * AW;    // [2][256][20]

    const int tid  = threadIdx.x;
    const int wid  = tid >> 5;
    const int lane = tid & 31;
    const int g    = lane >> 2;
    const int t    = lane & 3;
    const int wm   = wid >> 2;    // 0..1
    const int wn   = wid & 3;     // 0..3
    const int row0 = blockIdx.y * BM;
    const int col0 = blockIdx.x * BN;

    const float* Ab = A + (size_t)row0 * K;
    const float* Bb = B + (size_t)col0 * K;

    float acc[4][8][4];
    #pragma unroll
    for (int i = 0; i < 4; i++)
        #pragma unroll
        for (int j = 0; j < 8; j++)
            #pragma unroll
            for (int r = 0; r < 4; r++) acc[i][j][r] = 0.f;

    const int lr = tid >> 2;          // 0..63
    const int lc = (tid & 3) * 4;     // 0,4,8,12
    const uint32_t sa0 = smem_u32(Asf);
    const uint32_t sb0 = smem_u32(Bsf);

    auto load_tile = [&](int kc, int s) {
        const float* ag = Ab + kc * BK;
        const float* bg = Bb + kc * BK;
        #pragma unroll
        for (int i = 0; i < 2; i++) {
            const int r = lr + i * 64;
            cp_async16(sa0 + (s * AW + r * KSTRIDE + lc) * 4, ag + (size_t)r * K + lc);
        }
        #pragma unroll
        for (int i = 0; i < 4; i++) {
            const int r = lr + i * 64;
            cp_async16(sb0 + (s * BW + r * KSTRIDE + lc) * 4, bg + (size_t)r * K + lc);
        }
        CP_COMMIT();
    };

    const int NCH = K / BK;   // 64
    load_tile(0, 0);
    int buf = 0;

    for (int kc = 0; kc < NCH; kc++) {
        if (kc + 1 < NCH) {
            load_tile(kc + 1, buf ^ 1);
            CP_WAIT(1);
        } else {
            CP_WAIT(0);
        }
        __syncthreads();

        const float* Ac = Asf + buf * AW;
        const float* Bc = Bsf + buf * BW;

        #pragma unroll
        for (int ks = 0; ks < 2; ks++) {
            const int kb = ks * 8;
            uint32_t af[4][4], bf[8][2];
            #pragma unroll
            for (int i = 0; i < 4; i++) {
                const int m = wm * 64 + i * 16 + g;
                af[i][0] = f2tf32(Ac[m       * KSTRIDE + kb + t]);
                af[i][1] = f2tf32(Ac[(m + 8) * KSTRIDE + kb + t]);
                af[i][2] = f2tf32(Ac[m       * KSTRIDE + kb + t + 4]);
                af[i][3] = f2tf32(Ac[(m + 8) * KSTRIDE + kb + t + 4]);
            }
            #pragma unroll
            for (int j = 0; j < 8; j++) {
                const int n = wn * 64 + j * 8 + g;
                bf[j][0] = f2tf32(Bc[n * KSTRIDE + kb + t]);
                bf[j][1] = f2tf32(Bc[n * KSTRIDE + kb + t + 4]);
            }
            #pragma unroll
            for (int i = 0; i < 4; i++)
                #pragma unroll
                for (int j = 0; j < 8; j++)
                    mma_tf32(acc[i][j], af[i], bf[j]);
        }
        __syncthreads();
        buf ^= 1;
    }

    #pragma unroll
    for (int i = 0; i < 4; i++) {
        #pragma unroll
        for (int j = 0; j < 8; j++) {
            const int m = row0 + wm * 64 + i * 16 + g;
            const int n = col0 + wn * 64 + j * 8 + 2 * t;
            *(float2*)&C[(size_t)m * N + n]       = make_float2(acc[i][j][0], acc[i][j][1]);
            *(float2*)&C[(size_t)(m + 8) * N + n] = make_float2(acc[i][j][2], acc[i][j][3]);
        }
    }
}

// ---------------------------------------------------------------------------
// Tensor-core causal flash attention v3 (tf32 mma.sync).
// CTA: one (b,h) x 64 queries, 4 warps x 16-query warp tiles. Q in REGISTERS.
// 32-key K/V stages, cp.async double-buffered, raw fp32 K/V (HW truncation).
// Smem: K[2][32][68], V[2][32][72], P[64][68] = 52KB -> 3 CTAs/SM.
// ---------------------------------------------------------------------------
#define KST 68
#define VST 72
#define PST 68
#define KT  32   // keys per stage
#define QT  64   // queries per CTA

#define OFF_K 0
#define OFF_V (OFF_K + 2 * KT * KST)      // 4352
#define OFF_P (OFF_V + 2 * KT * VST)      // 8960
#define AWORDS (OFF_P + QT * PST)         // 13312
#define ASMEM (AWORDS * 4)                // 53248 bytes

__global__ void __launch_bounds__(128, 3) attn_tc(const float* __restrict__ qg,
                                                  const float* __restrict__ kg,
                                                  const float* __restrict__ vg,
                                                  float* __restrict__ og)
{
    uint32_t* smw = (uint32_t*)dynsmem;
    uint32_t* Ksm = smw + OFF_K;
    uint32_t* Vsm = smw + OFF_V;
    uint32_t* Ps  = smw + OFF_P;

    const int bh = blockIdx.y;
    const int b  = bh >> 4;
    const int h  = bh & 15;
    const int q0 = (gridDim.x - 1 - blockIdx.x) * QT;   // longest CTAs first
    const int tid = threadIdx.x;
    const int w = tid >> 5, lane = tid & 31;
    const int g = lane >> 2, t = lane & 3;

    const float* kbase = kg + ((size_t)(b * CS)) * CD + h * CDK;
    const float* vbase = vg + ((size_t)(b * CS)) * CD + h * CDK;

    // Q fragments straight into registers (RNA tf32). Rows 16w+g / +8.
    const float* qbase = qg + ((size_t)(b * CS + q0)) * CD + h * CDK;
    uint32_t qf[8][4];
    {
        const float* qr0 = qbase + (size_t)(16 * w + g) * CD;
        const float* qr1 = qbase + (size_t)(16 * w + g + 8) * CD;
        #pragma unroll
        for (int kc = 0; kc < 8; kc++) {
            qf[kc][0] = f2tf32(qr0[8 * kc + t]);
            qf[kc][1] = f2tf32(qr1[8 * kc + t]);
            qf[kc][2] = f2tf32(qr0[8 * kc + t + 4]);
            qf[kc][3] = f2tf32(qr1[8 * kc + t + 4]);
        }
    }

    // K/V stage loader: 32 rows x 256B each via cp.async (raw fp32)
    const uint32_t kb0 = smem_u32(Ksm);
    const uint32_t vb0 = smem_u32(Vsm);
    auto load_stage = [&](int kt_, int s) {
        const int k0 = kt_ * KT;
        const uint32_t kd = kb0 + s * (KT * KST * 4);
        const uint32_t vd = vb0 + s * (KT * VST * 4);
        #pragma unroll
        for (int i = 0; i < 4; i++) {
            int idx = tid + i * 128;
            int r = idx >> 4, c = idx & 15;
            cp_async16(kd + r * (KST * 4) + c * 16, kbase + (size_t)(k0 + r) * CD + c * 4);
        }
        #pragma unroll
        for (int i = 0; i < 4; i++) {
            int idx = tid + i * 128;
            int r = idx >> 4, c = idx & 15;
            cp_async16(vd + r * (VST * 4) + c * 16, vbase + (size_t)(k0 + r) * CD + c * 4);
        }
        CP_COMMIT();
    };

    float o[8][4];
    #pragma unroll
    for (int nt = 0; nt < 8; nt++)
        #pragma unroll
        for (int c = 0; c < 4; c++) o[nt][c] = 0.f;
    float mrow[2] = {-1e30f, -1e30f};
    float lrow[2] = {0.f, 0.f};

    const int ntiles = q0 / KT + 2;
    int buf = 0;
    load_stage(0, 0);

    for (int kt = 0; kt < ntiles; kt++) {
        const int k0 = kt * KT;
        if (kt + 1 < ntiles) {
            load_stage(kt + 1, buf ^ 1);
            CP_WAIT(1);
        } else {
            CP_WAIT(0);
        }
        __syncthreads();

        if (k0 <= q0 + 16 * w + 15) {
            const uint32_t* Kb = Ksm + buf * (KT * KST);
            const uint32_t* Vb = Vsm + buf * (KT * VST);

            // S = Q * K^T (K raw fp32 bits -> HW tf32 truncation)
            float s[4][4];
            #pragma unroll
            for (int nt = 0; nt < 4; nt++)
                #pragma unroll
                for (int c = 0; c < 4; c++) s[nt][c] = 0.f;

            #pragma unroll
            for (int kc = 0; kc < 8; kc++) {
                uint32_t bf[4][2];
                #pragma unroll
                for (int nt = 0; nt < 4; nt++) {
                    bf[nt][0] = Kb[(8 * nt + g) * KST + 8 * kc + t];
                    bf[nt][1] = Kb[(8 * nt + g) * KST + 8 * kc + t + 4];
                }
                #pragma unroll
                for (int nt = 0; nt < 4; nt++)
                    mma_tf32(s[nt], qf[kc], bf[nt]);
            }

            // scale + causal mask (diagonal stages only)
            const bool needmask = (k0 + KT - 1) > (q0 + 16 * w);
            #pragma unroll
            for (int nt = 0; nt < 4; nt++)
                #pragma unroll
                for (int c = 0; c < 4; c++) {
                    float sv = s[nt][c] * 0.125f;
                    if (needmask) {
                        int key = k0 + 8 * nt + 2 * t + (c & 1);
                        int qr  = q0 + 16 * w + 8 * (c >> 1) + g;
                        if (key > qr) sv = -1e30f;
                    }
                    s[nt][c] = sv;
                }

            // online softmax (row pair p=0,1 across the t-quad)
            #pragma unroll
            for (int p = 0; p < 2; p++) {
                float mx = -1e30f;
                #pragma unroll
                for (int nt = 0; nt < 4; nt++) {
                    mx = fmaxf(mx, s[nt][2 * p]);
                    mx = fmaxf(mx, s[nt][2 * p + 1]);
                }
                mx = fmaxf(mx, __shfl_xor_sync(0xffffffffu, mx, 1));
                mx = fmaxf(mx, __shfl_xor_sync(0xffffffffu, mx, 2));
                const float mnew = fmaxf(mrow[p], mx);
                const float corr = __expf(mrow[p] - mnew);
                mrow[p] = mnew;
                float ls = 0.f;
                #pragma unroll
                for (int nt = 0; nt < 4; nt++) {
                    float p0 = __expf(s[nt][2 * p]     - mnew);
                    float p1 = __expf(s[nt][2 * p + 1] - mnew);
                    s[nt][2 * p]     = p0;
                    s[nt][2 * p + 1] = p1;
                    ls += p0 + p1;
                }
                #pragma unroll
                for (int nt = 0; nt < 8; nt++) {
                    o[nt][2 * p]     *= corr;
                    o[nt][2 * p + 1] *= corr;
                }
                lrow[p] = lrow[p] * corr + ls;
            }

            // P -> smem (C-frag -> A-frag layout), RNA tf32
            #pragma unroll
            for (int p = 0; p < 2; p++) {
                const int row = 16 * w + 8 * p + g;
                #pragma unroll
                for (int nt = 0; nt < 4; nt++) {
                    uint2 pv = make_uint2(f2tf32(s[nt][2 * p]),
                                          f2tf32(s[nt][2 * p + 1]));
                    *(uint2*)&Ps[row * PST + 8 * nt + 2 * t] = pv;
                }
            }
            __syncwarp();

            // O += P * V (V transposed from smem, raw fp32 bits)
            #pragma unroll
            for (int kc = 0; kc < 4; kc++) {
                uint32_t af[4];
                af[0] = Ps[(16 * w + g)     * PST + 8 * kc + t];
                af[1] = Ps[(16 * w + g + 8) * PST + 8 * kc + t];
                af[2] = Ps[(16 * w + g)     * PST + 8 * kc + t + 4];
                af[3] = Ps[(16 * w + g + 8) * PST + 8 * kc + t + 4];
                #pragma unroll
                for (int nt = 0; nt < 8; nt++) {
                    uint32_t bf[2];
                    bf[0] = Vb[(8 * kc + t)     * VST + 8 * nt + g];
                    bf[1] = Vb[(8 * kc + t + 4) * VST + 8 * nt + g];
                    mma_tf32(o[nt], af, bf);
                }
            }
        }
        __syncthreads();
        buf ^= 1;
    }

    // finalize
    float inv[2];
    #pragma unroll
    for (int p = 0; p < 2; p++) {
        float lr = lrow[p];
        lr += __shfl_xor_sync(0xffffffffu, lr, 1);
        lr += __shfl_xor_sync(0xffffffffu, lr, 2);
        inv[p] = 1.f / lr;
    }

    float* obase = og + ((size_t)(b * CS + q0)) * CD + h * CDK;
    #pragma unroll
    for (int nt = 0; nt < 8; nt++) {
        const int r0 = 16 * w + g;
        *(float2*)(obase + (size_t)r0 * CD + 8 * nt + 2 * t) =
            make_float2(o[nt][0] * inv[0], o[nt][1] * inv[0]);
        *(float2*)(obase + (size_t)(r0 + 8) * CD + 8 * nt + 2 * t) =
            make_float2(o[nt][2] * inv[1], o[nt][3] * inv[1]);
    }
}

// ---------------------------------------------------------------------------
// Launch. Inputs: Q, K, V, mask(ignored), w_q, w_k, w_v, w_o. Out: [B,S,D] f32
// ---------------------------------------------------------------------------
extern "C" void kernel_launch(void* const* d_in, const int* in_sizes, int n_in,
                              void* d_out, int out_size)
{
    const float* Q  = (const float*)d_in[0];
    const float* K  = (const float*)d_in[1];
    const float* V  = (const float*)d_in[2];
    const float* wq = (const float*)d_in[4];
    const float* wk = (const float*)d_in[5];
    const float* wv = (const float*)d_in[6];
    const float* wo = (const float*)d_in[7];
    float* out = (float*)d_out;

    float *qb, *kb, *vb, *ab;
    cudaGetSymbolAddress((void**)&qb, g_q);
    cudaGetSymbolAddress((void**)&kb, g_k);
    cudaGetSymbolAddress((void**)&vb, g_v);
    cudaGetSymbolAddress((void**)&ab, g_a);

    cudaFuncSetAttribute(gemm_tc, cudaFuncAttributeMaxDynamicSharedMemorySize, GSMEM2);
    cudaFuncSetAttribute(attn_tc, cudaFuncAttributeMaxDynamicSharedMemorySize, ASMEM);

    dim3 gg(CD / BN, CM / BM);   // (4, 32) = 128 CTAs, single wave
    gemm_tc<<<gg, 256, GSMEM2>>>(Q, wq, qb, CM, CD, CD);
    gemm_tc<<<gg, 256, GSMEM2>>>(K, wk, kb, CM, CD, CD);
    gemm_tc<<<gg, 256, GSMEM2>>>(V, wv, vb, CM, CD, CD);

    attn_tc<<<dim3(CS / QT, CB * CH), 128, ASMEM>>>(qb, kb, vb, ab);

    gemm_tc<<<gg, 256, GSMEM2>>>(ab, wo, out, CM, CD, CD);
}

// round 10
// speedup vs baseline: 4.1872x; 1.0960x over previous
#include <cuda_runtime.h>
#include <cstdint>
#include <math.h>

// Problem constants
#define CB 2
#define CS 2048
#define CD 1024
#define CH 16
#define CDK 64
#define CM (CB*CS)   // 4096 rows

// Scratch (device globals: allocation-free rule)
__device__ float g_q[CB*CS*CD];
__device__ float g_k[CB*CS*CD];
__device__ float g_v[CB*CS*CD];
__device__ float g_a[CB*CS*CD];

// ---------------------------------------------------------------------------
// Helpers
// ---------------------------------------------------------------------------
__device__ __forceinline__ uint32_t smem_u32(const void* p) {
    uint32_t a;
    asm("{ .reg .u64 t; cvta.to.shared.u64 t, %1; cvt.u32.u64 %0, t; }" : "=r"(a) : "l"(p));
    return a;
}
__device__ __forceinline__ void cp_async16(uint32_t dst, const void* src) {
    asm volatile("cp.async.cg.shared.global [%0], [%1], 16;" :: "r"(dst), "l"(src) : "memory");
}
#define CP_COMMIT() asm volatile("cp.async.commit_group;" ::: "memory")
#define CP_WAIT(n)  asm volatile("cp.async.wait_group %0;" :: "n"(n) : "memory")

__device__ __forceinline__ uint32_t f2tf32(float x) {
    uint32_t o;
    asm("cvt.rna.tf32.f32 %0, %1;" : "=r"(o) : "f"(x));
    return o;
}
__device__ __forceinline__ void mma_tf32(float c[4], const uint32_t a[4], const uint32_t b[2]) {
    asm volatile("mma.sync.aligned.m16n8k8.row.col.f32.tf32.tf32.f32 "
                 "{%0,%1,%2,%3}, {%4,%5,%6,%7}, {%8,%9}, {%0,%1,%2,%3};"
                 : "+f"(c[0]), "+f"(c[1]), "+f"(c[2]), "+f"(c[3])
                 : "r"(a[0]), "r"(a[1]), "r"(a[2]), "r"(a[3]), "r"(b[0]), "r"(b[1]));
}
// ldmatrix x4: lanes 0-7 give row addrs of matrix0, 8-15 -> m1, 16-23 -> m2,
// 24-31 -> m3. Thread t holds (row = t>>2, 32-bit col = t&3) of each matrix.
__device__ __forceinline__ void ldsm_x4(uint32_t& r0, uint32_t& r1,
                                        uint32_t& r2, uint32_t& r3, uint32_t a) {
    asm volatile("ldmatrix.sync.aligned.m8n8.x4.shared.b16 {%0,%1,%2,%3}, [%4];"
                 : "=r"(r0), "=r"(r1), "=r"(r2), "=r"(r3) : "r"(a));
}

// Single dynamic smem symbol shared by both kernels.
extern __shared__ char dynsmem[];

// ---------------------------------------------------------------------------
// TF32 tensor-core GEMM v3: C[M,N] = A[M,K] * B[N,K]^T  (fp32 in/out)
// CTA tile 128x256, BK=16, 256 threads (8 warps = 2Mx4N), warp tile 64x64.
// Fragments via ldmatrix.x4 (16 LDSM per chunk vs 128 LDS). Double buffered.
// Grid (4, 32) = 128 CTAs -> single wave.
// ---------------------------------------------------------------------------
#define BM 128
#define BN 256
#define BK 16
#define KSTRIDE 20
#define AW (BM * KSTRIDE)        // 2560 words per A buffer
#define BW (BN * KSTRIDE)        // 5120 words per B buffer
#define GSMEM2 ((2 * AW + 2 * BW) * 4)   // 61440 bytes

__global__ void __launch_bounds__(256, 1) gemm_tc(const float* __restrict__ A,
                                                  const float* __restrict__ B,
                                                  float* __restrict__ C,
                                                  int M, int N, int K)
{
    float* smf = (float*)dynsmem;
    float* Asf = smf;             // [2][128][20]
    float* Bsf = smf + 2 * AW;    // [2][256][20]

    const int tid  = threadIdx.x;
    const int wid  = tid >> 5;
    const int lane = tid & 31;
    const int g    = lane >> 2;
    const int t    = lane & 3;
    const int wm   = wid >> 2;    // 0..1
    const int wn   = wid & 3;     // 0..3
    const int row0 = blockIdx.y * BM;
    const int col0 = blockIdx.x * BN;

    // ldmatrix per-lane offsets.
    // A pattern: mat0:(r+0,c+0) mat1:(r+8,c+0) mat2:(r+0,c+4) mat3:(r+8,c+4)
    const int al_row = ((lane >> 3) & 1) * 8 + (lane & 7);
    const int al_col = ((lane >> 4) & 1) * 4;
    // B pattern: mat0:(r+0,c+0) mat1:(r+0,c+4) mat2:(r+8,c+0) mat3:(r+8,c+4)
    const int bl_row = ((lane >> 4) & 1) * 8 + (lane & 7);
    const int bl_col = ((lane >> 3) & 1) * 4;

    const float* Ab = A + (size_t)row0 * K;
    const float* Bb = B + (size_t)col0 * K;

    float acc[4][8][4];
    #pragma unroll
    for (int i = 0; i < 4; i++)
        #pragma unroll
        for (int j = 0; j < 8; j++)
            #pragma unroll
            for (int r = 0; r < 4; r++) acc[i][j][r] = 0.f;

    const int lr = tid >> 2;          // 0..63
    const int lc = (tid & 3) * 4;     // 0,4,8,12
    const uint32_t sa0 = smem_u32(Asf);
    const uint32_t sb0 = smem_u32(Bsf);

    auto load_tile = [&](int kc, int s) {
        const float* ag = Ab + kc * BK;
        const float* bg = Bb + kc * BK;
        #pragma unroll
        for (int i = 0; i < 2; i++) {
            const int r = lr + i * 64;
            cp_async16(sa0 + (s * AW + r * KSTRIDE + lc) * 4, ag + (size_t)r * K + lc);
        }
        #pragma unroll
        for (int i = 0; i < 4; i++) {
            const int r = lr + i * 64;
            cp_async16(sb0 + (s * BW + r * KSTRIDE + lc) * 4, bg + (size_t)r * K + lc);
        }
        CP_COMMIT();
    };

    const int NCH = K / BK;   // 64
    load_tile(0, 0);
    int buf = 0;

    for (int kc = 0; kc < NCH; kc++) {
        if (kc + 1 < NCH) {
            load_tile(kc + 1, buf ^ 1);
            CP_WAIT(1);
        } else {
            CP_WAIT(0);
        }
        __syncthreads();

        const uint32_t Ac = sa0 + buf * (AW * 4);
        const uint32_t Bc = sb0 + buf * (BW * 4);

        #pragma unroll
        for (int ks = 0; ks < 2; ks++) {
            const int kb = ks * 8;
            uint32_t af[4][4], bf[8][2];
            const uint32_t aa = Ac + ((wm * 64 + al_row) * KSTRIDE + kb + al_col) * 4;
            #pragma unroll
            for (int i = 0; i < 4; i++) {
                uint32_t r0, r1, r2, r3;
                ldsm_x4(r0, r1, r2, r3, aa + i * (16 * KSTRIDE * 4));
                af[i][0] = f2tf32(__uint_as_float(r0));
                af[i][1] = f2tf32(__uint_as_float(r1));
                af[i][2] = f2tf32(__uint_as_float(r2));
                af[i][3] = f2tf32(__uint_as_float(r3));
            }
            const uint32_t ba = Bc + ((wn * 64 + bl_row) * KSTRIDE + kb + bl_col) * 4;
            #pragma unroll
            for (int jp = 0; jp < 4; jp++) {
                uint32_t r0, r1, r2, r3;
                ldsm_x4(r0, r1, r2, r3, ba + jp * (16 * KSTRIDE * 4));
                bf[2 * jp][0]     = f2tf32(__uint_as_float(r0));
                bf[2 * jp][1]     = f2tf32(__uint_as_float(r1));
                bf[2 * jp + 1][0] = f2tf32(__uint_as_float(r2));
                bf[2 * jp + 1][1] = f2tf32(__uint_as_float(r3));
            }
            #pragma unroll
            for (int i = 0; i < 4; i++)
                #pragma unroll
                for (int j = 0; j < 8; j++)
                    mma_tf32(acc[i][j], af[i], bf[j]);
        }
        __syncthreads();
        buf ^= 1;
    }

    #pragma unroll
    for (int i = 0; i < 4; i++) {
        #pragma unroll
        for (int j = 0; j < 8; j++) {
            const int m = row0 + wm * 64 + i * 16 + g;
            const int n = col0 + wn * 64 + j * 8 + 2 * t;
            *(float2*)&C[(size_t)m * N + n]       = make_float2(acc[i][j][0], acc[i][j][1]);
            *(float2*)&C[(size_t)(m + 8) * N + n] = make_float2(acc[i][j][2], acc[i][j][3]);
        }
    }
}

// ---------------------------------------------------------------------------
// Tensor-core causal flash attention v4 (tf32 mma.sync).
// CTA: one (b,h) x 64 queries, 4 warps x 16-query warp tiles. Q in registers.
// 64-key K/V stages (double buffered cp.async), K and P fragments via
// ldmatrix.x4, V via LDS (transposed read). Raw fp32 K/V (HW truncation).
// Smem: K[2][64][68], V[2][64][72], P[64][68] = 87KB -> 2 CTAs/SM.
// ---------------------------------------------------------------------------
#define KST 68
#define VST 72
#define PST 68
#define KT  64   // keys per stage
#define QT  64   // queries per CTA

#define OFF_K 0
#define OFF_V (OFF_K + 2 * KT * KST)      // 8704
#define OFF_P (OFF_V + 2 * KT * VST)      // 17920
#define AWORDS (OFF_P + QT * PST)         // 22272
#define ASMEM (AWORDS * 4)                // 89088 bytes

__global__ void __launch_bounds__(128, 2) attn_tc(const float* __restrict__ qg,
                                                  const float* __restrict__ kg,
                                                  const float* __restrict__ vg,
                                                  float* __restrict__ og)
{
    uint32_t* smw = (uint32_t*)dynsmem;
    uint32_t* Ksm = smw + OFF_K;
    uint32_t* Vsm = smw + OFF_V;
    uint32_t* Ps  = smw + OFF_P;

    const int bh = blockIdx.y;
    const int b  = bh >> 4;
    const int h  = bh & 15;
    const int q0 = (gridDim.x - 1 - blockIdx.x) * QT;   // longest CTAs first
    const int tid = threadIdx.x;
    const int w = tid >> 5, lane = tid & 31;
    const int g = lane >> 2, t = lane & 3;

    // ldmatrix per-lane offsets (A pattern for P, B pattern for K)
    const int al_row = ((lane >> 3) & 1) * 8 + (lane & 7);
    const int al_col = ((lane >> 4) & 1) * 4;
    const int bl_row = ((lane >> 4) & 1) * 8 + (lane & 7);
    const int bl_col = ((lane >> 3) & 1) * 4;

    const float* kbase = kg + ((size_t)(b * CS)) * CD + h * CDK;
    const float* vbase = vg + ((size_t)(b * CS)) * CD + h * CDK;

    // Q fragments in registers (RNA tf32). Rows 16w+g / +8.
    const float* qbase = qg + ((size_t)(b * CS + q0)) * CD + h * CDK;
    uint32_t qf[8][4];
    {
        const float* qr0 = qbase + (size_t)(16 * w + g) * CD;
        const float* qr1 = qbase + (size_t)(16 * w + g + 8) * CD;
        #pragma unroll
        for (int kc = 0; kc < 8; kc++) {
            qf[kc][0] = f2tf32(qr0[8 * kc + t]);
            qf[kc][1] = f2tf32(qr1[8 * kc + t]);
            qf[kc][2] = f2tf32(qr0[8 * kc + t + 4]);
            qf[kc][3] = f2tf32(qr1[8 * kc + t + 4]);
        }
    }

    // Stage loader: 64 rows x 256B each for K and V via cp.async (raw fp32)
    const uint32_t kb0 = smem_u32(Ksm);
    const uint32_t vb0 = smem_u32(Vsm);
    const uint32_t pb0 = smem_u32(Ps);
    auto load_stage = [&](int kt_, int s) {
        const int k0 = kt_ * KT;
        const uint32_t kd = kb0 + s * (KT * KST * 4);
        const uint32_t vd = vb0 + s * (KT * VST * 4);
        #pragma unroll
        for (int i = 0; i < 8; i++) {
            int idx = tid + i * 128;
            int r = idx >> 4, c = idx & 15;
            cp_async16(kd + r * (KST * 4) + c * 16, kbase + (size_t)(k0 + r) * CD + c * 4);
        }
        #pragma unroll
        for (int i = 0; i < 8; i++) {
            int idx = tid + i * 128;
            int r = idx >> 4, c = idx & 15;
            cp_async16(vd + r * (VST * 4) + c * 16, vbase + (size_t)(k0 + r) * CD + c * 4);
        }
        CP_COMMIT();
    };

    float o[8][4];
    #pragma unroll
    for (int nt = 0; nt < 8; nt++)
        #pragma unroll
        for (int c = 0; c < 4; c++) o[nt][c] = 0.f;
    float mrow[2] = {-1e30f, -1e30f};
    float lrow[2] = {0.f, 0.f};

    const int ntiles = q0 / KT + 1;
    int buf = 0;
    load_stage(0, 0);

    for (int kt = 0; kt < ntiles; kt++) {
        const int k0 = kt * KT;
        if (kt + 1 < ntiles) {
            load_stage(kt + 1, buf ^ 1);
            CP_WAIT(1);
        } else {
            CP_WAIT(0);
        }
        __syncthreads();

        if (k0 <= q0 + 16 * w + 15) {
            const uint32_t Kb = kb0 + buf * (KT * KST * 4);
            const uint32_t* Vb = Vsm + buf * (KT * VST);

            // S = Q * K^T  (K fragments via ldmatrix; raw fp32 -> HW tf32)
            float s[8][4];
            #pragma unroll
            for (int nt = 0; nt < 8; nt++)
                #pragma unroll
                for (int c = 0; c < 4; c++) s[nt][c] = 0.f;

            #pragma unroll
            for (int kc = 0; kc < 8; kc++) {
                uint32_t bf[8][2];
                const uint32_t ka = Kb + (bl_row * KST + 8 * kc + bl_col) * 4;
                #pragma unroll
                for (int p_ = 0; p_ < 4; p_++)
                    ldsm_x4(bf[2 * p_][0], bf[2 * p_][1],
                            bf[2 * p_ + 1][0], bf[2 * p_ + 1][1],
                            ka + p_ * (16 * KST * 4));
                #pragma unroll
                for (int nt = 0; nt < 8; nt++)
                    mma_tf32(s[nt], qf[kc], bf[nt]);
            }

            // scale + causal mask (diagonal tiles only)
            const bool needmask = (k0 + KT - 1) > (q0 + 16 * w);
            #pragma unroll
            for (int nt = 0; nt < 8; nt++)
                #pragma unroll
                for (int c = 0; c < 4; c++) {
                    float sv = s[nt][c] * 0.125f;
                    if (needmask) {
                        int key = k0 + 8 * nt + 2 * t + (c & 1);
                        int qr  = q0 + 16 * w + 8 * (c >> 1) + g;
                        if (key > qr) sv = -1e30f;
                    }
                    s[nt][c] = sv;
                }

            // online softmax (row pair p=0,1 across the t-quad)
            #pragma unroll
            for (int p = 0; p < 2; p++) {
                float mx = -1e30f;
                #pragma unroll
                for (int nt = 0; nt < 8; nt++) {
                    mx = fmaxf(mx, s[nt][2 * p]);
                    mx = fmaxf(mx, s[nt][2 * p + 1]);
                }
                mx = fmaxf(mx, __shfl_xor_sync(0xffffffffu, mx, 1));
                mx = fmaxf(mx, __shfl_xor_sync(0xffffffffu, mx, 2));
                const float mnew = fmaxf(mrow[p], mx);
                const float corr = __expf(mrow[p] - mnew);
                mrow[p] = mnew;
                float ls = 0.f;
                #pragma unroll
                for (int nt = 0; nt < 8; nt++) {
                    float p0 = __expf(s[nt][2 * p]     - mnew);
                    float p1 = __expf(s[nt][2 * p + 1] - mnew);
                    s[nt][2 * p]     = p0;
                    s[nt][2 * p + 1] = p1;
                    ls += p0 + p1;
                }
                #pragma unroll
                for (int nt = 0; nt < 8; nt++) {
                    o[nt][2 * p]     *= corr;
                    o[nt][2 * p + 1] *= corr;
                }
                lrow[p] = lrow[p] * corr + ls;
            }

            // P -> smem (C-frag -> A-frag layout), RNA tf32
            #pragma unroll
            for (int p = 0; p < 2; p++) {
                const int row = 16 * w + 8 * p + g;
                #pragma unroll
                for (int nt = 0; nt < 8; nt++) {
                    uint2 pv = make_uint2(f2tf32(s[nt][2 * p]),
                                          f2tf32(s[nt][2 * p + 1]));
                    *(uint2*)&Ps[row * PST + 8 * nt + 2 * t] = pv;
                }
            }
            __syncwarp();

            // O += P * V  (P via ldmatrix, V transposed LDS, raw fp32 bits)
            #pragma unroll
            for (int kc = 0; kc < 8; kc++) {
                uint32_t af[4];
                ldsm_x4(af[0], af[1], af[2], af[3],
                        pb0 + ((16 * w + al_row) * PST + 8 * kc + al_col) * 4);
                #pragma unroll
                for (int nt = 0; nt < 8; nt++) {
                    uint32_t bf[2];
                    bf[0] = Vb[(8 * kc + t)     * VST + 8 * nt + g];
                    bf[1] = Vb[(8 * kc + t + 4) * VST + 8 * nt + g];
                    mma_tf32(o[nt], af, bf);
                }
            }
        }
        __syncthreads();
        buf ^= 1;
    }

    // finalize
    float inv[2];
    #pragma unroll
    for (int p = 0; p < 2; p++) {
        float lr = lrow[p];
        lr += __shfl_xor_sync(0xffffffffu, lr, 1);
        lr += __shfl_xor_sync(0xffffffffu, lr, 2);
        inv[p] = 1.f / lr;
    }

    float* obase = og + ((size_t)(b * CS + q0)) * CD + h * CDK;
    #pragma unroll
    for (int nt = 0; nt < 8; nt++) {
        const int r0 = 16 * w + g;
        *(float2*)(obase + (size_t)r0 * CD + 8 * nt + 2 * t) =
            make_float2(o[nt][0] * inv[0], o[nt][1] * inv[0]);
        *(float2*)(obase + (size_t)(r0 + 8) * CD + 8 * nt + 2 * t) =
            make_float2(o[nt][2] * inv[1], o[nt][3] * inv[1]);
    }
}

// ---------------------------------------------------------------------------
// Launch. Inputs: Q, K, V, mask(ignored), w_q, w_k, w_v, w_o. Out: [B,S,D] f32
// ---------------------------------------------------------------------------
extern "C" void kernel_launch(void* const* d_in, const int* in_sizes, int n_in,
                              void* d_out, int out_size)
{
    const float* Q  = (const float*)d_in[0];
    const float* K  = (const float*)d_in[1];
    const float* V  = (const float*)d_in[2];
    const float* wq = (const float*)d_in[4];
    const float* wk = (const float*)d_in[5];
    const float* wv = (const float*)d_in[6];
    const float* wo = (const float*)d_in[7];
    float* out = (float*)d_out;

    float *qb, *kb, *vb, *ab;
    cudaGetSymbolAddress((void**)&qb, g_q);
    cudaGetSymbolAddress((void**)&kb, g_k);
    cudaGetSymbolAddress((void**)&vb, g_v);
    cudaGetSymbolAddress((void**)&ab, g_a);

    cudaFuncSetAttribute(gemm_tc, cudaFuncAttributeMaxDynamicSharedMemorySize, GSMEM2);
    cudaFuncSetAttribute(attn_tc, cudaFuncAttributeMaxDynamicSharedMemorySize, ASMEM);

    dim3 gg(CD / BN, CM / BM);   // (4, 32) = 128 CTAs, single wave
    gemm_tc<<<gg, 256, GSMEM2>>>(Q, wq, qb, CM, CD, CD);
    gemm_tc<<<gg, 256, GSMEM2>>>(K, wk, kb, CM, CD, CD);
    gemm_tc<<<gg, 256, GSMEM2>>>(V, wv, vb, CM, CD, CD);

    attn_tc<<<dim3(CS / QT, CB * CH), 128, ASMEM>>>(qb, kb, vb, ab);

    gemm_tc<<<gg, 256, GSMEM2>>>(ab, wo, out, CM, CD, CD);
}